// round 4
// baseline (speedup 1.0000x reference)
#include <cuda_runtime.h>
#include <cstdint>

// GumbelSinkhorn, SMEM-resident: B=128, N=512 rows (agents), M=512 cols (tasks).
// Cluster of 8 CTAs per batch; CTA k owns column strip [64k, 64k+64) for ALL rows,
// held in shared memory across all 9 normalization passes.
//   - col sums (softmax over rows, axis=1): CTA-local
//   - row sums (softmax over cols, axis=2): 8-CTA DSMEM reduction
// Single global read (logits) + single global write (out).

#define BB 128
#define NN 512
#define MM 512
#define NSTRIP 8
#define SCOLS 64
#define NWARP 32          // 1024 threads

struct Smem {
    float E[NN * SCOLS];        // resident strip (exp-domain)
    float prow[NN];             // partial row sums (this CTA's 64 cols)
    float rtot[NN];             // reciprocal TOTAL row sums (cluster-reduced)
    float cpart[NWARP][SCOLS];  // per-warp column-sum partials
    float ctot[SCOLS];          // reciprocal column sums (local)
};

__device__ __forceinline__ uint32_t smem_u32(const void* p) {
    return (uint32_t)__cvta_generic_to_shared(p);
}
__device__ __forceinline__ float ld_dsmem(uint32_t addr, uint32_t rank) {
    uint32_t ra;
    asm("mapa.shared::cluster.u32 %0, %1, %2;" : "=r"(ra) : "r"(addr), "r"(rank));
    float v;
    asm volatile("ld.shared::cluster.f32 %0, [%1];" : "=f"(v) : "r"(ra));
    return v;
}
__device__ __forceinline__ void st_dsmem(uint32_t addr, uint32_t rank, float v) {
    uint32_t ra;
    asm("mapa.shared::cluster.u32 %0, %1, %2;" : "=r"(ra) : "r"(addr), "r"(rank));
    asm volatile("st.shared::cluster.f32 [%0], %1;" :: "r"(ra), "f"(v));
}
__device__ __forceinline__ void cluster_sync() {
    asm volatile("barrier.cluster.arrive.aligned;" ::: "memory");
    asm volatile("barrier.cluster.wait.aligned;" ::: "memory");
}
__device__ __forceinline__ float warp_sum(float v) {
    v += __shfl_xor_sync(0xffffffffu, v, 16);
    v += __shfl_xor_sync(0xffffffffu, v, 8);
    v += __shfl_xor_sync(0xffffffffu, v, 4);
    v += __shfl_xor_sync(0xffffffffu, v, 2);
    v += __shfl_xor_sync(0xffffffffu, v, 1);
    return v;
}

// Cluster-wide row-sum reduction: prow (all CTAs) -> rtot (all CTAs, reciprocal).
// CTA k reduces rows [64k, 64k+64) and broadcasts reciprocals to all 8 ranks.
__device__ __forceinline__ void reduce_rsum(Smem& S, int k, int tid) {
    cluster_sync();                      // all partials visible
    if (tid < 512) {
        int row = k * SCOLS + (tid >> 3);
        int src = tid & 7;
        float p = ld_dsmem(smem_u32(&S.prow[row]), (uint32_t)src);
        p += __shfl_xor_sync(0xffffffffu, p, 1);
        p += __shfl_xor_sync(0xffffffffu, p, 2);
        p += __shfl_xor_sync(0xffffffffu, p, 4);
        float rt = 1.0f / p;             // inf for inactive rows (never consumed)
        st_dsmem(smem_u32(&S.rtot[row]), (uint32_t)src, rt);
    }
    cluster_sync();                      // all totals visible
}

__global__ void __cluster_dims__(NSTRIP, 1, 1) __launch_bounds__(1024, 1)
sinkhorn_kernel(const float* __restrict__ logits,
                const int* __restrict__ fa,
                const int* __restrict__ ta,
                float* __restrict__ out) {
    extern __shared__ char sraw[];
    Smem& S = *reinterpret_cast<Smem*>(sraw);

    int b = blockIdx.y;
    int k = blockIdx.x;                  // strip rank == cluster rank
    int na = fa[b];
    int nt = ta[b];
    int ncols = nt - k * SCOLS;
    ncols = ncols < 0 ? 0 : (ncols > SCOLS ? SCOLS : ncols);

    int tid = threadIdx.x;
    int w = tid >> 5, lane = tid & 31;
    int cl = lane * 2;                   // this lane's local column pair
    bool a0 = (cl     < ncols);
    bool a1 = (cl + 1 < ncols);

    // zero prow so rows >= na read as 0 in the cluster reduction
    for (int i = tid; i < NN; i += 1024) S.prow[i] = 0.f;
    __syncthreads();

    const float* Lb = logits + (size_t)b * NN * MM + k * SCOLS;

    // ---- init: E = exp(logits) on active cells; prow partials
    for (int r = w; r < na; r += NWARP) {
        float2 e = *(const float2*)(Lb + r * MM + cl);
        float e0 = a0 ? __expf(e.x) : 0.f;
        float e1 = a1 ? __expf(e.y) : 0.f;
        S.E[r * SCOLS + cl]     = e0;
        S.E[r * SCOLS + cl + 1] = e1;
        float s = warp_sum(e0 + e1);
        if (lane == 0) S.prow[r] = s;
    }
    __syncthreads();
    reduce_rsum(S, k, tid);

    // ---- 5 iterations of (row softmax -> col softmax)
    #pragma unroll 1
    for (int it = 0; it < 5; it++) {
        // rownorm: E' = exp(E * rtot[r]); accumulate column partials
        float acc0 = 0.f, acc1 = 0.f;
        for (int r = w; r < na; r += NWARP) {
            float rt = S.rtot[r];
            float e0 = S.E[r * SCOLS + cl];
            float e1 = S.E[r * SCOLS + cl + 1];
            e0 = a0 ? __expf(e0 * rt) : 0.f;
            e1 = a1 ? __expf(e1 * rt) : 0.f;
            S.E[r * SCOLS + cl]     = e0;
            S.E[r * SCOLS + cl + 1] = e1;
            acc0 += e0; acc1 += e1;
        }
        S.cpart[w][cl]     = acc0;
        S.cpart[w][cl + 1] = acc1;
        __syncthreads();
        if (tid < SCOLS) {
            float s = 0.f;
            #pragma unroll
            for (int ww = 0; ww < NWARP; ww++) s += S.cpart[ww][tid];
            S.ctot[tid] = 1.0f / s;      // inf only if column inactive/empty
        }
        __syncthreads();

        if (it == 4) break;              // uniform across cluster

        // colnorm: E' = exp(E * ctot[c]); prow partials
        float ct0 = S.ctot[cl], ct1 = S.ctot[cl + 1];
        for (int r = w; r < na; r += NWARP) {
            float e0 = S.E[r * SCOLS + cl];
            float e1 = S.E[r * SCOLS + cl + 1];
            e0 = a0 ? __expf(e0 * ct0) : 0.f;
            e1 = a1 ? __expf(e1 * ct1) : 0.f;
            S.E[r * SCOLS + cl]     = e0;
            S.E[r * SCOLS + cl + 1] = e1;
            float s = warp_sum(e0 + e1);
            if (lane == 0) S.prow[r] = s;
        }
        __syncthreads();
        reduce_rsum(S, k, tid);
    }

    // ---- finalize: out = E * ctot (5th axis-1 softmax), zeros outside mask.
    float ct0 = a0 ? S.ctot[cl]     : 0.f;   // 0 so 0*0=0 (avoid 0*inf)
    float ct1 = a1 ? S.ctot[cl + 1] : 0.f;
    float* Ob = out + (size_t)b * NN * MM + k * SCOLS;
    for (int r = w; r < NN; r += NWARP) {
        float2 v = make_float2(0.f, 0.f);
        if (r < na) {
            v.x = S.E[r * SCOLS + cl]     * ct0;
            v.y = S.E[r * SCOLS + cl + 1] * ct1;
        }
        *(float2*)(Ob + r * MM + cl) = v;
    }
}

extern "C" void kernel_launch(void* const* d_in, const int* in_sizes, int n_in,
                              void* d_out, int out_size) {
    const float* logits = (const float*)d_in[0];
    const int*   fa     = (const int*)d_in[1];
    const int*   ta     = (const int*)d_in[2];
    float*       out    = (float*)d_out;

    cudaFuncSetAttribute(sinkhorn_kernel,
                         cudaFuncAttributeMaxDynamicSharedMemorySize,
                         (int)sizeof(Smem));

    dim3 grid(NSTRIP, BB);
    dim3 block(1024);
    sinkhorn_kernel<<<grid, block, sizeof(Smem)>>>(logits, fa, ta, out);
}

// round 5
// speedup vs baseline: 1.0592x; 1.0592x over previous
#include <cuda_runtime.h>
#include <cstdint>

// GumbelSinkhorn: B=128, N=512 rows (agents), M=512 cols (tasks), tau=1, 5 iters.
// Invariant: g_E holds exp(x_k) on the active [na, nt] region.
// g_rsum / g_csum hold RECIPROCAL sums. Work-list compaction over active strips.

#define BB 128
#define NN 512
#define MM 512

__device__ float g_E[(size_t)BB * NN * MM];
__device__ float g_rsum[BB * NN];
__device__ float g_csum[BB * MM];
__device__ int   g_itemsR[BB * 16];   // row strips of 32 rows: (b<<5)|strip
__device__ int   g_itemsC[BB * 8];    // col strips of 64 cols: (b<<4)|strip
__device__ int   g_cntR;
__device__ int   g_cntC;

__device__ __forceinline__ float warp_sum(float v) {
    v += __shfl_xor_sync(0xffffffffu, v, 16);
    v += __shfl_xor_sync(0xffffffffu, v, 8);
    v += __shfl_xor_sync(0xffffffffu, v, 4);
    v += __shfl_xor_sync(0xffffffffu, v, 2);
    v += __shfl_xor_sync(0xffffffffu, v, 1);
    return v;
}

// ---------------------------------------------------------------------------
// setup: build compacted work lists of active strips. 1 CTA, 128 threads.
__global__ void setup_kernel(const int* __restrict__ fa,
                             const int* __restrict__ ta) {
    int b = threadIdx.x;                       // one thread per batch
    int na = fa[b], nt = ta[b];
    bool act = (na > 0) && (nt > 0);
    int cR = act ? (na + 31) >> 5 : 0;
    int cC = act ? (nt + 63) >> 6 : 0;
    int lane = b & 31, w = b >> 5;
    int iR = cR, iC = cC;                      // inclusive scan within warp
    #pragma unroll
    for (int d = 1; d < 32; d <<= 1) {
        int tR = __shfl_up_sync(0xffffffffu, iR, d);
        int tC = __shfl_up_sync(0xffffffffu, iC, d);
        if (lane >= d) { iR += tR; iC += tC; }
    }
    __shared__ int wR[4], wC[4];
    if (lane == 31) { wR[w] = iR; wC[w] = iC; }
    __syncthreads();
    int baseR = 0, baseC = 0;
    for (int k = 0; k < w; k++) { baseR += wR[k]; baseC += wC[k]; }
    int offR = baseR + iR - cR;
    int offC = baseC + iC - cC;
    for (int s = 0; s < cR; s++) g_itemsR[offR + s] = (b << 5) | s;
    for (int s = 0; s < cC; s++) g_itemsC[offC + s] = (b << 4) | s;
    if (b == 127) { g_cntR = baseR + iR; g_cntC = baseC + iC; }
}

// ---------------------------------------------------------------------------
// init: E = exp(logits) on active cells; rsum = 1/rowsum.
// Row-strip items (32 rows). block 256: 8 warps, 4 rows/warp, float4 cols.
__global__ void __launch_bounds__(256) init_kernel(
        const float* __restrict__ logits,
        const int* __restrict__ fa,
        const int* __restrict__ ta) {
    int cnt = g_cntR;
    int w = threadIdx.x >> 5, lane = threadIdx.x & 31;
    int cb0 = lane * 4;
    for (int it = blockIdx.x; it < cnt; it += gridDim.x) {
        int item = g_itemsR[it];
        int b = item >> 5, r0 = (item & 31) << 5;
        int na = fa[b], nt = ta[b];
        const float* Lb = logits + (size_t)b * NN * MM;
        float*       Eb = g_E    + (size_t)b * NN * MM;
        for (int rr = w; rr < 32; rr += 8) {
            int r = r0 + rr;
            if (r >= na) break;
            float4 acc = make_float4(0.f, 0.f, 0.f, 0.f);
            #pragma unroll
            for (int k = 0; k < 4; k++) {
                int cb = cb0 + k * 128;
                if (cb >= nt) continue;
                int nv = nt - cb;
                if (nv >= 4) {
                    float4 e = *(const float4*)(Lb + r * MM + cb);
                    e.x = __expf(e.x); e.y = __expf(e.y);
                    e.z = __expf(e.z); e.w = __expf(e.w);
                    *(float4*)(Eb + r * MM + cb) = e;
                    acc.x += e.x; acc.y += e.y; acc.z += e.z; acc.w += e.w;
                } else {
                    for (int j = 0; j < nv; j++) {
                        float e = __expf(Lb[r * MM + cb + j]);
                        Eb[r * MM + cb + j] = e;
                        ((float*)&acc)[j] += e;
                    }
                }
            }
            float s = warp_sum(acc.x + acc.y + acc.z + acc.w);
            if (lane == 0) g_rsum[b * NN + r] = 1.0f / s;
        }
    }
}

// ---------------------------------------------------------------------------
// rownorm: E' = exp(E * rsum[r]); csum = 1/colsum(E').
// Col-strip items (64 cols). block 256: lane owns 2 cols, rows stride 8,
// 8-deep software pipeline (8 float2 + 8 rsum loads in flight).
__global__ void __launch_bounds__(256) rownorm_kernel(
        const int* __restrict__ fa,
        const int* __restrict__ ta) {
    __shared__ float2 s[8][32];
    int cnt = g_cntC;
    int tid = threadIdx.x;
    int w = tid >> 5, lane = tid & 31;
    for (int it = blockIdx.x; it < cnt; it += gridDim.x) {
        int item = g_itemsC[it];
        int b = item >> 4, c0 = (item & 15) << 6;
        int na = fa[b], nt = ta[b];
        int c = c0 + lane * 2;
        float*       Eb = g_E    + (size_t)b * NN * MM;
        const float* rs = g_rsum + b * NN;
        float2 acc = make_float2(0.f, 0.f);

        if (c + 1 < nt) {
            int r = w;
            for (; r + 56 < na; r += 64) {
                float2 e0 = *(const float2*)(Eb + (r     ) * MM + c);
                float2 e1 = *(const float2*)(Eb + (r +  8) * MM + c);
                float2 e2 = *(const float2*)(Eb + (r + 16) * MM + c);
                float2 e3 = *(const float2*)(Eb + (r + 24) * MM + c);
                float2 e4 = *(const float2*)(Eb + (r + 32) * MM + c);
                float2 e5 = *(const float2*)(Eb + (r + 40) * MM + c);
                float2 e6 = *(const float2*)(Eb + (r + 48) * MM + c);
                float2 e7 = *(const float2*)(Eb + (r + 56) * MM + c);
                float i0 = rs[r],      i1 = rs[r +  8], i2 = rs[r + 16], i3 = rs[r + 24];
                float i4 = rs[r + 32], i5 = rs[r + 40], i6 = rs[r + 48], i7 = rs[r + 56];
                e0.x = __expf(e0.x * i0); e0.y = __expf(e0.y * i0);
                e1.x = __expf(e1.x * i1); e1.y = __expf(e1.y * i1);
                e2.x = __expf(e2.x * i2); e2.y = __expf(e2.y * i2);
                e3.x = __expf(e3.x * i3); e3.y = __expf(e3.y * i3);
                e4.x = __expf(e4.x * i4); e4.y = __expf(e4.y * i4);
                e5.x = __expf(e5.x * i5); e5.y = __expf(e5.y * i5);
                e6.x = __expf(e6.x * i6); e6.y = __expf(e6.y * i6);
                e7.x = __expf(e7.x * i7); e7.y = __expf(e7.y * i7);
                *(float2*)(Eb + (r     ) * MM + c) = e0;
                *(float2*)(Eb + (r +  8) * MM + c) = e1;
                *(float2*)(Eb + (r + 16) * MM + c) = e2;
                *(float2*)(Eb + (r + 24) * MM + c) = e3;
                *(float2*)(Eb + (r + 32) * MM + c) = e4;
                *(float2*)(Eb + (r + 40) * MM + c) = e5;
                *(float2*)(Eb + (r + 48) * MM + c) = e6;
                *(float2*)(Eb + (r + 56) * MM + c) = e7;
                acc.x += ((e0.x + e1.x) + (e2.x + e3.x)) + ((e4.x + e5.x) + (e6.x + e7.x));
                acc.y += ((e0.y + e1.y) + (e2.y + e3.y)) + ((e4.y + e5.y) + (e6.y + e7.y));
            }
            for (; r < na; r += 8) {
                float2 e = *(const float2*)(Eb + r * MM + c);
                float inv = rs[r];
                e.x = __expf(e.x * inv); e.y = __expf(e.y * inv);
                *(float2*)(Eb + r * MM + c) = e;
                acc.x += e.x; acc.y += e.y;
            }
        } else if (c < nt) {
            for (int r = w; r < na; r += 8) {
                float e = Eb[r * MM + c];
                e = __expf(e * rs[r]);
                Eb[r * MM + c] = e;
                acc.x += e;
            }
        }

        s[w][lane] = acc;
        __syncthreads();
        if (tid < 64) {
            int ln = tid >> 1, comp = tid & 1;
            float sum = 0.f;
            #pragma unroll
            for (int k = 0; k < 8; k++) sum += ((const float*)&s[k][ln])[comp];
            int cc = c0 + tid;
            if (cc < nt) g_csum[b * MM + cc] = 1.0f / sum;
        }
        __syncthreads();
    }
}

// ---------------------------------------------------------------------------
// colnorm: E' = exp(E * csum[c]); rsum = 1/rowsum(E').
// Row-strip items (32 rows). block 256, float4 cols.
__global__ void __launch_bounds__(256) colnorm_kernel(
        const int* __restrict__ fa,
        const int* __restrict__ ta) {
    int cnt = g_cntR;
    int w = threadIdx.x >> 5, lane = threadIdx.x & 31;
    int cb0 = lane * 4;
    for (int it = blockIdx.x; it < cnt; it += gridDim.x) {
        int item = g_itemsR[it];
        int b = item >> 5, r0 = (item & 31) << 5;
        int na = fa[b], nt = ta[b];
        float*       Eb = g_E    + (size_t)b * NN * MM;
        const float* cs = g_csum + b * MM;
        for (int rr = w; rr < 32; rr += 8) {
            int r = r0 + rr;
            if (r >= na) break;
            float4 acc = make_float4(0.f, 0.f, 0.f, 0.f);
            #pragma unroll
            for (int k = 0; k < 4; k++) {
                int cb = cb0 + k * 128;
                if (cb >= nt) continue;
                int nv = nt - cb;
                if (nv >= 4) {
                    float4 e  = *(const float4*)(Eb + r * MM + cb);
                    float4 c4 = *(const float4*)(cs + cb);
                    e.x = __expf(e.x * c4.x); e.y = __expf(e.y * c4.y);
                    e.z = __expf(e.z * c4.z); e.w = __expf(e.w * c4.w);
                    *(float4*)(Eb + r * MM + cb) = e;
                    acc.x += e.x; acc.y += e.y; acc.z += e.z; acc.w += e.w;
                } else {
                    for (int j = 0; j < nv; j++) {
                        float e = Eb[r * MM + cb + j];
                        e = __expf(e * cs[cb + j]);
                        Eb[r * MM + cb + j] = e;
                        ((float*)&acc)[j] += e;
                    }
                }
            }
            float s = warp_sum(acc.x + acc.y + acc.z + acc.w);
            if (lane == 0) g_rsum[b * NN + r] = 1.0f / s;
        }
    }
}

// ---------------------------------------------------------------------------
// finalize: out = E * csum in mask, 0 outside. Full [N,M]. 2048 CTAs, block 256.
__global__ void __launch_bounds__(256) finalize_kernel(
        float* __restrict__ out,
        const int* __restrict__ fa,
        const int* __restrict__ ta) {
    int b = blockIdx.x >> 4;
    int r0 = (blockIdx.x & 15) << 5;
    int na = fa[b], nt = ta[b];
    int w = threadIdx.x >> 5, lane = threadIdx.x & 31;
    const float* Eb = g_E    + (size_t)b * NN * MM;
    const float* cs = g_csum + b * MM;
    float*       Ob = out    + (size_t)b * NN * MM;
    int cb0 = lane * 4;
    for (int rr = w; rr < 32; rr += 8) {
        int r = r0 + rr;
        bool rv = (r < na);
        #pragma unroll
        for (int k = 0; k < 4; k++) {
            int cb = cb0 + k * 128;
            float4 v = make_float4(0.f, 0.f, 0.f, 0.f);
            if (rv && cb < nt) {
                int nv = nt - cb;
                if (nv >= 4) {
                    float4 e  = *(const float4*)(Eb + r * MM + cb);
                    float4 c4 = *(const float4*)(cs + cb);
                    v.x = e.x * c4.x; v.y = e.y * c4.y;
                    v.z = e.z * c4.z; v.w = e.w * c4.w;
                } else {
                    for (int j = 0; j < nv; j++)
                        ((float*)&v)[j] = Eb[r * MM + cb + j] * cs[cb + j];
                }
            }
            *(float4*)(Ob + r * MM + cb) = v;
        }
    }
}

extern "C" void kernel_launch(void* const* d_in, const int* in_sizes, int n_in,
                              void* d_out, int out_size) {
    const float* logits = (const float*)d_in[0];
    const int*   fa     = (const int*)d_in[1];
    const int*   ta     = (const int*)d_in[2];
    float*       out    = (float*)d_out;

    setup_kernel<<<1, 128>>>(fa, ta);
    init_kernel<<<2048, 256>>>(logits, fa, ta);
    for (int i = 0; i < 5; i++) {
        rownorm_kernel<<<1024, 256>>>(fa, ta);
        if (i < 4) colnorm_kernel<<<2048, 256>>>(fa, ta);
    }
    finalize_kernel<<<2048, 256>>>(out, fa, ta);
}

// round 7
// speedup vs baseline: 1.4221x; 1.3426x over previous
#include <cuda_runtime.h>
#include <cstdint>

// GumbelSinkhorn: B=128, N=512 rows (agents), M=512 cols (tasks), tau=1, 5 iters.
// Fused-pair schedule: I=[exp+rownorm1], P_k=[colnorm_k+rownorm_{k+1}] (k=1..4),
// F=[colnorm5 -> out]. Row strips of 32 rows live in SMEM between the two
// sweeps of each pair; column sums accumulate across strips via atomicAdd.
// Accumulator selection is BY INDEX inside device code (device symbols must
// not have their addresses taken on the host).

#define BB 128
#define NN 512
#define MM 512

__device__ float g_E[(size_t)BB * NN * MM];   // exp-domain state
__device__ float g_acc[5][BB * MM];           // colsum accumulators per pass
__device__ int   g_items[BB * 16];            // active row strips: (b<<4)|strip
__device__ int   g_cnt;

__device__ __forceinline__ float warp_sum(float v) {
    v += __shfl_xor_sync(0xffffffffu, v, 16);
    v += __shfl_xor_sync(0xffffffffu, v, 8);
    v += __shfl_xor_sync(0xffffffffu, v, 4);
    v += __shfl_xor_sync(0xffffffffu, v, 2);
    v += __shfl_xor_sync(0xffffffffu, v, 1);
    return v;
}

// ---------------------------------------------------------------------------
// setup: zero accumulators (grid-stride) + build active-strip list (block 0, warp 0).
__global__ void setup_kernel(const int* __restrict__ fa,
                             const int* __restrict__ ta) {
    float4* p = (float4*)&g_acc[0][0];
    int total4 = 5 * BB * MM / 4;
    for (int i = blockIdx.x * blockDim.x + threadIdx.x; i < total4;
         i += gridDim.x * blockDim.x)
        p[i] = make_float4(0.f, 0.f, 0.f, 0.f);

    if (blockIdx.x == 0 && threadIdx.x < 32) {
        int lane = threadIdx.x;
        int carry = 0;
        for (int g = 0; g < 4; g++) {
            int b = g * 32 + lane;
            int na = fa[b], nt = ta[b];
            int c = (na > 0 && nt > 0) ? (na + 31) >> 5 : 0;
            int inc = c;
            #pragma unroll
            for (int d = 1; d < 32; d <<= 1) {
                int t = __shfl_up_sync(0xffffffffu, inc, d);
                if (lane >= d) inc += t;
            }
            int off = carry + inc - c;
            for (int s = 0; s < c; s++) g_items[off + s] = (b << 4) | s;
            carry += __shfl_sync(0xffffffffu, inc, 31);
        }
        if (lane == 0) g_cnt = carry;
    }
}

// ---------------------------------------------------------------------------
// Shared tail of I and P: sweep2 (rownorm) from SMEM + column-partial reduction.
// sm layout: strip rows [32][512]; after sweep2, rows 0..15 reused as cpart[16][512].
__device__ __forceinline__ void sweep2_and_reduce(
        float* sm, float* Eb, float* dst_acc, int b,
        int r0, int na, int nt, int w, int lane, int tid,
        const float rinv[2]) {
    float4 cacc[4];
    #pragma unroll
    for (int k = 0; k < 4; k++) cacc[k] = make_float4(0.f, 0.f, 0.f, 0.f);
    #pragma unroll
    for (int rr = 0; rr < 2; rr++) {
        int r = w + rr * 16, gr = r0 + r;
        if (gr >= na) continue;
        float ri = rinv[rr];
        #pragma unroll
        for (int k = 0; k < 4; k++) {
            int cb = lane * 4 + k * 128;
            if (cb >= nt) continue;
            float4 e = *(const float4*)(sm + r * MM + cb);
            float4 o;
            o.x = __expf(e.x * ri);
            o.y = (cb + 1 < nt) ? __expf(e.y * ri) : 0.f;
            o.z = (cb + 2 < nt) ? __expf(e.z * ri) : 0.f;
            o.w = (cb + 3 < nt) ? __expf(e.w * ri) : 0.f;
            *(float4*)(Eb + gr * MM + cb) = o;
            cacc[k].x += o.x; cacc[k].y += o.y;
            cacc[k].z += o.z; cacc[k].w += o.w;
        }
    }
    __syncthreads();                      // strip reads done -> reuse as cpart
    #pragma unroll
    for (int k = 0; k < 4; k++)
        *(float4*)(sm + w * MM + lane * 4 + k * 128) = cacc[k];
    __syncthreads();
    float s = 0.f;
    #pragma unroll
    for (int ww = 0; ww < 16; ww++) s += sm[ww * MM + tid];
    if (tid < nt) atomicAdd(dst_acc + b * MM + tid, s);
    __syncthreads();                      // before next item reuses sm
}

// ---------------------------------------------------------------------------
// I: E1 = exp(softmax_row(exp(logits))) pipeline start; partials -> g_acc[0].
__global__ void __launch_bounds__(512) init_pair_kernel(
        const float* __restrict__ logits,
        const int* __restrict__ fa,
        const int* __restrict__ ta) {
    extern __shared__ float sm[];
    int cnt = g_cnt;
    int tid = threadIdx.x, w = tid >> 5, lane = tid & 31;
    for (int it = blockIdx.x; it < cnt; it += gridDim.x) {
        int item = g_items[it];
        int b = item >> 4, r0 = (item & 15) << 5;
        int na = fa[b], nt = ta[b];
        const float* Lb = logits + (size_t)b * NN * MM;
        float*       Eb = g_E    + (size_t)b * NN * MM;
        float rinv[2];
        #pragma unroll
        for (int rr = 0; rr < 2; rr++) {
            int r = w + rr * 16, gr = r0 + r;
            rinv[rr] = 0.f;
            if (gr >= na) continue;
            float rowacc = 0.f;
            #pragma unroll
            for (int k = 0; k < 4; k++) {
                int cb = lane * 4 + k * 128;
                float4 o = make_float4(0.f, 0.f, 0.f, 0.f);
                if (cb < nt) {
                    float4 e = *(const float4*)(Lb + gr * MM + cb);
                    o.x = __expf(e.x);
                    o.y = (cb + 1 < nt) ? __expf(e.y) : 0.f;
                    o.z = (cb + 2 < nt) ? __expf(e.z) : 0.f;
                    o.w = (cb + 3 < nt) ? __expf(e.w) : 0.f;
                }
                *(float4*)(sm + r * MM + cb) = o;
                rowacc += (o.x + o.y) + (o.z + o.w);
            }
            float s = warp_sum(rowacc);
            rinv[rr] = __fdividef(1.f, s);
        }
        sweep2_and_reduce(sm, Eb, &g_acc[0][0], b, r0, na, nt, w, lane, tid, rinv);
    }
}

// ---------------------------------------------------------------------------
// P: colnorm (E*1/csum -> exp) then rownorm; partials -> g_acc[p+1].
__global__ void __launch_bounds__(512) pair_kernel(
        int p,
        const int* __restrict__ fa,
        const int* __restrict__ ta) {
    extern __shared__ float sm[];
    const float* src_acc = &g_acc[p][0];
    float*       dst_acc = &g_acc[p + 1][0];
    int cnt = g_cnt;
    int tid = threadIdx.x, w = tid >> 5, lane = tid & 31;
    for (int it = blockIdx.x; it < cnt; it += gridDim.x) {
        int item = g_items[it];
        int b = item >> 4, r0 = (item & 15) << 5;
        int na = fa[b], nt = ta[b];
        const float* CS = src_acc + b * MM;
        float*       Eb = g_E + (size_t)b * NN * MM;

        float4 ics[4];
        #pragma unroll
        for (int k = 0; k < 4; k++) {
            int cb = lane * 4 + k * 128;
            ics[k] = make_float4(0.f, 0.f, 0.f, 0.f);
            if (cb < nt) {
                float4 s4 = *(const float4*)(CS + cb);
                ics[k].x = __fdividef(1.f, s4.x);
                if (cb + 1 < nt) ics[k].y = __fdividef(1.f, s4.y);
                if (cb + 2 < nt) ics[k].z = __fdividef(1.f, s4.z);
                if (cb + 3 < nt) ics[k].w = __fdividef(1.f, s4.w);
            }
        }

        float rinv[2];
        #pragma unroll
        for (int rr = 0; rr < 2; rr++) {
            int r = w + rr * 16, gr = r0 + r;
            rinv[rr] = 0.f;
            if (gr >= na) continue;
            float rowacc = 0.f;
            #pragma unroll
            for (int k = 0; k < 4; k++) {
                int cb = lane * 4 + k * 128;
                float4 o = make_float4(0.f, 0.f, 0.f, 0.f);
                if (cb < nt) {
                    float4 e = *(const float4*)(Eb + gr * MM + cb);
                    o.x = __expf(e.x * ics[k].x);
                    o.y = (cb + 1 < nt) ? __expf(e.y * ics[k].y) : 0.f;
                    o.z = (cb + 2 < nt) ? __expf(e.z * ics[k].z) : 0.f;
                    o.w = (cb + 3 < nt) ? __expf(e.w * ics[k].w) : 0.f;
                }
                *(float4*)(sm + r * MM + cb) = o;
                rowacc += (o.x + o.y) + (o.z + o.w);
            }
            float s = warp_sum(rowacc);
            rinv[rr] = __fdividef(1.f, s);
        }
        sweep2_and_reduce(sm, Eb, dst_acc, b, r0, na, nt, w, lane, tid, rinv);
    }
}

// ---------------------------------------------------------------------------
// F: out = E * 1/csum (g_acc[4]) inside mask, 0 outside. Full [N, M] coverage.
__global__ void __launch_bounds__(512) final_kernel(
        float* __restrict__ out,
        const int* __restrict__ fa,
        const int* __restrict__ ta) {
    int b = blockIdx.x >> 4, r0 = (blockIdx.x & 15) << 5;
    int na = fa[b], nt = ta[b];
    int tid = threadIdx.x, w = tid >> 5, lane = tid & 31;
    const float* Eb = g_E + (size_t)b * NN * MM;
    const float* CS = &g_acc[4][0] + b * MM;
    float*       Ob = out + (size_t)b * NN * MM;

    float4 ics[4];
    #pragma unroll
    for (int k = 0; k < 4; k++) {
        int cb = lane * 4 + k * 128;
        ics[k] = make_float4(0.f, 0.f, 0.f, 0.f);
        if (cb < nt) {
            float4 s4 = *(const float4*)(CS + cb);
            ics[k].x = __fdividef(1.f, s4.x);
            if (cb + 1 < nt) ics[k].y = __fdividef(1.f, s4.y);
            if (cb + 2 < nt) ics[k].z = __fdividef(1.f, s4.z);
            if (cb + 3 < nt) ics[k].w = __fdividef(1.f, s4.w);
        }
    }
    #pragma unroll
    for (int rr = 0; rr < 2; rr++) {
        int gr = r0 + w + rr * 16;
        bool rv = (gr < na);
        #pragma unroll
        for (int k = 0; k < 4; k++) {
            int cb = lane * 4 + k * 128;
            float4 v = make_float4(0.f, 0.f, 0.f, 0.f);
            if (rv && cb < nt) {
                float4 e = *(const float4*)(Eb + gr * MM + cb);
                v.x = e.x * ics[k].x; v.y = e.y * ics[k].y;
                v.z = e.z * ics[k].z; v.w = e.w * ics[k].w;
            }
            *(float4*)(Ob + gr * MM + cb) = v;
        }
    }
}

extern "C" void kernel_launch(void* const* d_in, const int* in_sizes, int n_in,
                              void* d_out, int out_size) {
    const float* logits = (const float*)d_in[0];
    const int*   fa     = (const int*)d_in[1];
    const int*   ta     = (const int*)d_in[2];
    float*       out    = (float*)d_out;

    const int SMEM = 32 * MM * sizeof(float);   // 64 KB strip
    cudaFuncSetAttribute(init_pair_kernel,
                         cudaFuncAttributeMaxDynamicSharedMemorySize, SMEM);
    cudaFuncSetAttribute(pair_kernel,
                         cudaFuncAttributeMaxDynamicSharedMemorySize, SMEM);

    setup_kernel<<<256, 256>>>(fa, ta);
    init_pair_kernel<<<2048, 512, SMEM>>>(logits, fa, ta);
    for (int p = 0; p < 4; p++)
        pair_kernel<<<2048, 512, SMEM>>>(p, fa, ta);
    final_kernel<<<2048, 512>>>(out, fa, ta);
}

// round 8
// speedup vs baseline: 1.7489x; 1.2298x over previous
#include <cuda_runtime.h>
#include <cstdint>

// GumbelSinkhorn: B=128, N=512 rows (agents), M=512 cols (tasks), tau=1, 5 iters.
// Fused-pair schedule, register-resident: one row per warp (16 floats/thread),
// sweep1 = exp(E/csum) [axis-1 softmax start], warp-reduce row sum,
// sweep2 = exp(v/rowsum) [axis-2], single global write. Column partials via
// one SMEM transpose + atomicAdd into g_acc[p+1].
// 16-row strips; items compacted in setup. 10 softmax passes total.

#define BB 128
#define NN 512
#define MM 512

__device__ float g_E[(size_t)BB * NN * MM];   // exp-domain state
__device__ float g_acc[5][BB * MM];           // colsum accumulators per stage
__device__ int   g_items[BB * 32];            // 16-row strips: (b<<5)|strip
__device__ int   g_cnt;

__device__ __forceinline__ float warp_sum(float v) {
    v += __shfl_xor_sync(0xffffffffu, v, 16);
    v += __shfl_xor_sync(0xffffffffu, v, 8);
    v += __shfl_xor_sync(0xffffffffu, v, 4);
    v += __shfl_xor_sync(0xffffffffu, v, 2);
    v += __shfl_xor_sync(0xffffffffu, v, 1);
    return v;
}

// ---------------------------------------------------------------------------
// setup: zero accumulators + build active-strip list (warp 0 of block 0).
__global__ void setup_kernel(const int* __restrict__ fa,
                             const int* __restrict__ ta) {
    float4* p = (float4*)&g_acc[0][0];
    int total4 = 5 * BB * MM / 4;
    for (int i = blockIdx.x * blockDim.x + threadIdx.x; i < total4;
         i += gridDim.x * blockDim.x)
        p[i] = make_float4(0.f, 0.f, 0.f, 0.f);

    if (blockIdx.x == 0 && threadIdx.x < 32) {
        int lane = threadIdx.x;
        int carry = 0;
        for (int g = 0; g < 4; g++) {
            int b = g * 32 + lane;
            int na = fa[b], nt = ta[b];
            int c = (na > 0 && nt > 0) ? (na + 15) >> 4 : 0;   // 16-row strips
            int inc = c;
            #pragma unroll
            for (int d = 1; d < 32; d <<= 1) {
                int t = __shfl_up_sync(0xffffffffu, inc, d);
                if (lane >= d) inc += t;
            }
            int off = carry + inc - c;
            for (int s = 0; s < c; s++) g_items[off + s] = (b << 5) | s;
            carry += __shfl_sync(0xffffffffu, inc, 31);
        }
        if (lane == 0) g_cnt = carry;
    }
}

// ---------------------------------------------------------------------------
// Column-partial reduce + atomic accumulate (shared tail).
// sm[w][col] already holds this warp-row's post-sweep2 values (zeros if row
// inactive). 512 threads reduce 16 warps each, atomicAdd to dst.
__device__ __forceinline__ void col_reduce(float (*sm)[MM], float* dst,
                                           int b, int nt, int tid) {
    __syncthreads();
    float s = 0.f;
    #pragma unroll
    for (int ww = 0; ww < 16; ww++) s += sm[ww][tid];
    if (tid < nt) atomicAdd(dst + b * MM + tid, s);
    __syncthreads();
}

// ---------------------------------------------------------------------------
// I: E0=exp(logits); pass1 (axis2): E1=exp(E0*rinv_row); colsums(E1)->g_acc[0].
__global__ void __launch_bounds__(512) init_pair_kernel(
        const float* __restrict__ logits,
        const int* __restrict__ fa,
        const int* __restrict__ ta) {
    __shared__ float sm[16][MM];
    int cnt = g_cnt;
    int tid = threadIdx.x, w = tid >> 5, lane = tid & 31;
    for (int it = blockIdx.x; it < cnt; it += gridDim.x) {
        int item = g_items[it];
        int b = item >> 5, r0 = (item & 31) << 4;
        int na = fa[b], nt = ta[b];
        float* Eb = g_E + (size_t)b * NN * MM;
        int gr = r0 + w;
        bool rowv = (gr < na);

        float4 v[4];
        float rowacc = 0.f;
        #pragma unroll
        for (int k = 0; k < 4; k++) {
            int cb = lane * 4 + k * 128;
            v[k] = make_float4(0.f, 0.f, 0.f, 0.f);
            if (rowv && cb < nt) {
                float4 e = *(const float4*)(logits + (size_t)b * NN * MM + gr * MM + cb);
                v[k].x = __expf(e.x);
                v[k].y = (cb + 1 < nt) ? __expf(e.y) : 0.f;
                v[k].z = (cb + 2 < nt) ? __expf(e.z) : 0.f;
                v[k].w = (cb + 3 < nt) ? __expf(e.w) : 0.f;
                rowacc += (v[k].x + v[k].y) + (v[k].z + v[k].w);
            }
        }
        float rinv = __fdividef(1.f, warp_sum(rowacc));
        #pragma unroll
        for (int k = 0; k < 4; k++) {
            int cb = lane * 4 + k * 128;
            float4 o = make_float4(0.f, 0.f, 0.f, 0.f);
            if (rowv && cb < nt) {
                o.x = __expf(v[k].x * rinv);
                o.y = (cb + 1 < nt) ? __expf(v[k].y * rinv) : 0.f;
                o.z = (cb + 2 < nt) ? __expf(v[k].z * rinv) : 0.f;
                o.w = (cb + 3 < nt) ? __expf(v[k].w * rinv) : 0.f;
                *(float4*)(Eb + gr * MM + cb) = o;
            }
            *(float4*)(&sm[w][cb]) = o;
        }
        col_reduce(sm, &g_acc[0][0], b, nt, tid);
    }
}

// ---------------------------------------------------------------------------
// P_p: sweep1 axis1 using csums g_acc[p]; sweep2 axis2; colsums -> g_acc[p+1].
__global__ void __launch_bounds__(512) pair_kernel(
        int p,
        const int* __restrict__ fa,
        const int* __restrict__ ta) {
    __shared__ float sm[16][MM];
    const float* src = &g_acc[p][0];
    float*       dst = &g_acc[p + 1][0];
    int cnt = g_cnt;
    int tid = threadIdx.x, w = tid >> 5, lane = tid & 31;
    for (int it = blockIdx.x; it < cnt; it += gridDim.x) {
        int item = g_items[it];
        int b = item >> 5, r0 = (item & 31) << 4;
        int na = fa[b], nt = ta[b];
        const float* CS = src + b * MM;
        float*       Eb = g_E + (size_t)b * NN * MM;
        int gr = r0 + w;
        bool rowv = (gr < na);

        float4 v[4];
        float rowacc = 0.f;
        #pragma unroll
        for (int k = 0; k < 4; k++) {
            int cb = lane * 4 + k * 128;
            v[k] = make_float4(0.f, 0.f, 0.f, 0.f);
            if (rowv && cb < nt) {
                float4 s4 = *(const float4*)(CS + cb);
                float4 e  = *(const float4*)(Eb + gr * MM + cb);
                v[k].x = __expf(__fdividef(e.x, s4.x));
                v[k].y = (cb + 1 < nt) ? __expf(__fdividef(e.y, s4.y)) : 0.f;
                v[k].z = (cb + 2 < nt) ? __expf(__fdividef(e.z, s4.z)) : 0.f;
                v[k].w = (cb + 3 < nt) ? __expf(__fdividef(e.w, s4.w)) : 0.f;
                rowacc += (v[k].x + v[k].y) + (v[k].z + v[k].w);
            }
        }
        float rinv = __fdividef(1.f, warp_sum(rowacc));
        #pragma unroll
        for (int k = 0; k < 4; k++) {
            int cb = lane * 4 + k * 128;
            float4 o = make_float4(0.f, 0.f, 0.f, 0.f);
            if (rowv && cb < nt) {
                o.x = __expf(v[k].x * rinv);
                o.y = (cb + 1 < nt) ? __expf(v[k].y * rinv) : 0.f;
                o.z = (cb + 2 < nt) ? __expf(v[k].z * rinv) : 0.f;
                o.w = (cb + 3 < nt) ? __expf(v[k].w * rinv) : 0.f;
                *(float4*)(Eb + gr * MM + cb) = o;
            }
            *(float4*)(&sm[w][cb]) = o;
        }
        col_reduce(sm, dst, b, nt, tid);
    }
}

// ---------------------------------------------------------------------------
// F: pass10 (axis1, no exp): out = E9 / csum (g_acc[4]) in mask, 0 outside.
// Full [N, M] coverage. grid 4096 (b<<5|strip16), block 512, warp per row.
__global__ void __launch_bounds__(512) final_kernel(
        float* __restrict__ out,
        const int* __restrict__ fa,
        const int* __restrict__ ta) {
    int b = blockIdx.x >> 5, r0 = (blockIdx.x & 31) << 4;
    int na = fa[b], nt = ta[b];
    int tid = threadIdx.x, w = tid >> 5, lane = tid & 31;
    const float* Eb = g_E + (size_t)b * NN * MM;
    const float* CS = &g_acc[4][0] + b * MM;
    float*       Ob = out + (size_t)b * NN * MM;
    int gr = r0 + w;
    bool rowv = (gr < na);
    #pragma unroll
    for (int k = 0; k < 4; k++) {
        int cb = lane * 4 + k * 128;
        float4 o = make_float4(0.f, 0.f, 0.f, 0.f);
        if (rowv && cb < nt) {
            float4 s4 = *(const float4*)(CS + cb);
            float4 e  = *(const float4*)(Eb + gr * MM + cb);
            o.x = __fdividef(e.x, s4.x);
            o.y = (cb + 1 < nt) ? __fdividef(e.y, s4.y) : 0.f;
            o.z = (cb + 2 < nt) ? __fdividef(e.z, s4.z) : 0.f;
            o.w = (cb + 3 < nt) ? __fdividef(e.w, s4.w) : 0.f;
        }
        *(float4*)(Ob + gr * MM + cb) = o;
    }
}

extern "C" void kernel_launch(void* const* d_in, const int* in_sizes, int n_in,
                              void* d_out, int out_size) {
    const float* logits = (const float*)d_in[0];
    const int*   fa     = (const int*)d_in[1];
    const int*   ta     = (const int*)d_in[2];
    float*       out    = (float*)d_out;

    setup_kernel<<<256, 256>>>(fa, ta);
    init_pair_kernel<<<2048, 512>>>(logits, fa, ta);
    for (int p = 0; p < 4; p++)
        pair_kernel<<<2048, 512>>>(p, fa, ta);
    final_kernel<<<4096, 512>>>(out, fa, ta);
}